// round 1
// baseline (speedup 1.0000x reference)
#include <cuda_runtime.h>
#include <cstdint>
#include <cstddef>

#define Bb 16
#define Nn 307
#define Tt 12
#define NSTEP 11
#define Rr (Bb*Nn)   // 4912
#define HH 64

// ---------------- device scratch (no allocation allowed) ----------------
__device__ float d_A[Nn*Nn];
__device__ float d_agcW[(size_t)Nn*2*64*64];   // [n][k][i][o]
__device__ float d_agcb[Nn*64];
__device__ float d_h[Rr*64];
__device__ float d_z[Rr*64];
__device__ float d_kh[Rr*64];
__device__ float d_kz[Rr*64];
__device__ float d_acch[Rr*64];
__device__ float d_accz[Rr*64];
__device__ float d_x1g[Rr*64];
__device__ float d_y[Rr*64];
__device__ float d_x2[Rr*64];

__device__ __forceinline__ float fast_tanh(float x){
    // tanh(x) = 1 - 2/(exp(2x)+1); robust for |x| large, ~1e-7 abs error
    return 1.f - __fdividef(2.f, __expf(2.f*x) + 1.f);
}

// ---------------- precompute kernels ----------------
__global__ void k_A(const float* __restrict__ gE){
    __shared__ float s[Nn];
    __shared__ float red[128];
    int n = blockIdx.x, tid = threadIdx.x;
    float en[8];
    #pragma unroll
    for (int d=0; d<8; d++) en[d] = gE[n*8+d];
    for (int m=tid; m<Nn; m+=128){
        float acc = 0.f;
        #pragma unroll
        for (int d=0; d<8; d++) acc += en[d]*gE[m*8+d];
        s[m] = fmaxf(acc, 0.f);
    }
    __syncthreads();
    float mx = -1e30f;
    for (int m=tid; m<Nn; m+=128) mx = fmaxf(mx, s[m]);
    red[tid] = mx; __syncthreads();
    for (int o=64;o>0;o>>=1){ if (tid<o) red[tid]=fmaxf(red[tid],red[tid+o]); __syncthreads(); }
    mx = red[0]; __syncthreads();
    float sum = 0.f;
    for (int m=tid; m<Nn; m+=128){ float e = expf(s[m]-mx); s[m]=e; sum+=e; }
    red[tid]=sum; __syncthreads();
    for (int o=64;o>0;o>>=1){ if (tid<o) red[tid]+=red[tid+o]; __syncthreads(); }
    float inv = 1.f/red[0];
    for (int m=tid; m<Nn; m+=128) d_A[(size_t)n*Nn+m] = s[m]*inv;
}

__global__ void k_agcW(const float* __restrict__ gE, const float* __restrict__ gWpool){
    int idx = blockIdx.x*256 + threadIdx.x;
    if (idx >= Nn*8192) return;
    int n = idx >> 13;
    int rest = idx & 8191;
    float acc = 0.f;
    #pragma unroll
    for (int d=0; d<8; d++) acc += gE[n*8+d]*gWpool[(size_t)d*8192 + rest];
    d_agcW[idx] = acc;
}

__global__ void k_agcb(const float* __restrict__ gE, const float* __restrict__ gbpool){
    int idx = blockIdx.x*256 + threadIdx.x;
    if (idx >= Nn*64) return;
    int n = idx >> 6, o = idx & 63;
    float acc = 0.f;
    #pragma unroll
    for (int d=0; d<8; d++) acc += gE[n*8+d]*gbpool[d*64+o];
    d_agcb[idx] = acc;
}

__global__ void k_init(const float* __restrict__ coeff_a,
                       const float* __restrict__ hW, const float* __restrict__ hb,
                       const float* __restrict__ zW, const float* __restrict__ zb){
    int idx = blockIdx.x*256 + threadIdx.x;
    if (idx >= Rr*64) return;
    int r = idx >> 6, h = idx & 63;
    float x0 = coeff_a[(size_t)r*(NSTEP*2) + 0];
    float x1 = coeff_a[(size_t)r*(NSTEP*2) + 1];
    d_h[idx] = x0*hW[h] + x1*hW[64+h] + hb[h];
    d_z[idx] = x0*zW[h] + x1*zW[64+h] + zb[h];
    d_acch[idx] = 0.f;
    d_accz[idx] = 0.f;
}

// ---------------- per-stage kernels ----------------
// state eval + func_f chain (-> kh, acch) + g layer1 (-> x1g)
__global__ void k_fg1(const float* __restrict__ times,
                      const float* __restrict__ cb, const float* __restrict__ cc, const float* __restrict__ cd,
                      const float* __restrict__ fWin, const float* __restrict__ fbin,
                      const float* __restrict__ fWmid, const float* __restrict__ fbmid,
                      const float* __restrict__ fWout, const float* __restrict__ fbout,
                      const float* __restrict__ gWin, const float* __restrict__ gbin,
                      int step, int stage){
    int r = blockIdx.x, t = threadIdx.x;
    __shared__ float sh[64], sz[64], sx1[64], sx2[64];
    float t0 = times[step], t1 = times[step+1];
    float dt = t1 - t0;
    float c  = (stage==0) ? 0.f : ((stage==3) ? dt : 0.5f*dt);
    float tv = (stage==0) ? t0  : ((stage==3) ? t1 : (t0 + 0.5f*dt));
    float w  = (stage==1 || stage==2) ? 2.f : 1.f;
    size_t base = (size_t)r*64 + t;
    float hv = d_h[base], zv = d_z[base];
    if (stage){ hv += c*d_kh[base]; zv += c*d_kz[base]; }
    sh[t] = hv; sz[t] = zv;
    __syncthreads();
    float acc  = fbin[t];
    float accg = gbin[t];
    #pragma unroll 8
    for (int i=0;i<64;i++){
        acc  = fmaf(sh[i], fWin[i*64+t], acc);
        accg = fmaf(sz[i], gWin[i*64+t], accg);
    }
    d_x1g[base] = fmaxf(accg, 0.f);
    sx1[t] = fmaxf(acc, 0.f);
    __syncthreads();
    acc = fbmid[t];
    #pragma unroll 8
    for (int i=0;i<64;i++) acc = fmaf(sx1[i], fWmid[i*64+t], acc);
    sx2[t] = fmaxf(acc, 0.f);
    __syncthreads();
    float2 a3 = ((const float2*)fbout)[t];
    #pragma unroll 8
    for (int i=0;i<64;i++){
        float2 wv = ((const float2*)fWout)[i*64+t];
        a3.x = fmaf(sx2[i], wv.x, a3.x);
        a3.y = fmaf(sx2[i], wv.y, a3.y);
    }
    // spline derivative dX at tv
    int idx = 0;
    #pragma unroll
    for (int j=1; j<=NSTEP-1; j++) if (times[j] <= tv) idx = j;
    float frac = tv - times[idx];
    size_t cbase = ((size_t)r*NSTEP + idx)*2;
    float dX0 = cb[cbase]   + (cc[cbase]   + cd[cbase]  *frac)*frac;
    float dX1 = cb[cbase+1] + (cc[cbase+1] + cd[cbase+1]*frac)*frac;
    float dh = fast_tanh(a3.x)*dX0 + fast_tanh(a3.y)*dX1;
    d_kh[base] = dh;
    d_acch[base] += w*dh;
}

// graph aggregation: y[b,n,:] = sum_m A[n,m] * x1g[b,m,:]
#define AGG_SMEM (Nn*64*4)
__global__ void k_agg(){
    extern __shared__ float xs[];           // [307*64]
    int b = blockIdx.y, ch = blockIdx.x;
    int tid = threadIdx.x;
    const float* src = &d_x1g[(size_t)b*Nn*64];
    for (int i=tid; i<Nn*64; i+=256) xs[i] = src[i];
    __syncthreads();
    int t = tid & 63, rg = tid >> 6;
    int n0 = ch*39;
    int n1 = n0 + 39; if (n1 > Nn) n1 = Nn;
    for (int n = n0 + rg; n < n1; n += 4){
        const float* Arow = &d_A[(size_t)n*Nn];
        float acc = 0.f;
        int m = 0;
        #pragma unroll 4
        for (; m+4 <= Nn; m += 4){
            acc = fmaf(Arow[m],   xs[(m)*64+t],   acc);
            acc = fmaf(Arow[m+1], xs[(m+1)*64+t], acc);
            acc = fmaf(Arow[m+2], xs[(m+2)*64+t], acc);
            acc = fmaf(Arow[m+3], xs[(m+3)*64+t], acc);
        }
        for (; m<Nn; m++) acc = fmaf(Arow[m], xs[m*64+t], acc);
        d_y[((size_t)b*Nn + n)*64 + t] = acc;
    }
}

// AGC per node: x2 = relu(x1g @ agcW[n,0] + y @ agcW[n,1] + agcb[n])
__global__ void k_x2(){
    __shared__ float sx[16*64], sy[16*64];
    int n = blockIdx.x, tid = threadIdx.x;
    for (int u=tid; u<16*64; u+=256){
        int b = u >> 6, i = u & 63;
        size_t g = ((size_t)b*Nn + n)*64 + i;
        sx[u] = d_x1g[g];
        sy[u] = d_y[g];
    }
    __syncthreads();
    int o = tid & 63, bg = tid >> 6;    // bg: 0..3, handles b = bg*4 + j
    const float* W0 = &d_agcW[(size_t)n*8192];
    const float* W1 = W0 + 4096;
    float bias = d_agcb[n*64+o];
    float acc[4] = {bias, bias, bias, bias};
    #pragma unroll 4
    for (int i=0;i<64;i++){
        float w0 = W0[i*64+o];
        float w1 = W1[i*64+o];
        #pragma unroll
        for (int j=0;j<4;j++){
            int b = bg*4 + j;
            acc[j] = fmaf(sx[b*64+i], w0, acc[j]);
            acc[j] = fmaf(sy[b*64+i], w1, acc[j]);
        }
    }
    #pragma unroll
    for (int j=0;j<4;j++){
        int b = bg*4 + j;
        d_x2[((size_t)b*Nn + n)*64 + o] = fmaxf(acc[j], 0.f);
    }
}

// big fused kernel: G = x2 @ g_W_out + b ; dz[r,i] = sum_j tanh(G[r,i*64+j]) * dh[r,j]
#define GZ_XS   (64*132)
#define GZ_WS   (64*256)
#define GZ_DHS  (128*65)
#define GZ_RED  (128*4*4)
#define GZ_SMEM ((GZ_XS + GZ_WS + GZ_DHS + GZ_RED)*4)

__global__ void k_gz(const float* __restrict__ gWout, const float* __restrict__ gbout,
                     const float* __restrict__ times, int step, int stage){
    extern __shared__ float sm[];
    float* Xs  = sm;                    // [k][row] stride 132
    float* Ws  = Xs + GZ_XS;            // [k][col] stride 256
    float* Dhs = Ws + GZ_WS;            // [row][j] stride 65
    float* red = Dhs + GZ_DHS;
    int tid = threadIdx.x;
    int r0 = blockIdx.x * 128;
    int c0 = blockIdx.y * 256;

    for (int u=tid; u<128*64; u+=256){
        int row = u >> 6, k = u & 63;
        int r = r0 + row;
        Xs[k*132 + row] = (r < Rr) ? d_x2[(size_t)r*64 + k] : 0.f;
    }
    for (int u=tid; u<64*256; u+=256){
        int k = u >> 8, cc2 = u & 255;
        Ws[u] = gWout[(size_t)k*4096 + c0 + cc2];
    }
    for (int u=tid; u<128*64; u+=256){
        int row = u >> 6, j = u & 63;
        int r = r0 + row;
        Dhs[row*65 + j] = (r < Rr) ? d_kh[(size_t)r*64 + j] : 0.f;
    }
    __syncthreads();

    int tx = tid & 15, ty = tid >> 4;
    unsigned long long acc[8][8];
    #pragma unroll
    for (int i=0;i<8;i++)
        #pragma unroll
        for (int j=0;j<8;j++) acc[i][j] = 0ull;

    #pragma unroll 4
    for (int k=0;k<64;k++){
        unsigned long long a2[8];
        #pragma unroll
        for (int i=0;i<8;i++){
            float av = Xs[k*132 + ty*8 + i];
            asm("mov.b64 %0, {%1, %1};" : "=l"(a2[i]) : "f"(av));
        }
        const unsigned long long* bp =
            reinterpret_cast<const unsigned long long*>(&Ws[k*256 + tx*16]);
        unsigned long long bv[8];
        #pragma unroll
        for (int j=0;j<8;j++) bv[j] = bp[j];
        #pragma unroll
        for (int i=0;i<8;i++)
            #pragma unroll
            for (int j=0;j<8;j++)
                asm("fma.rn.f32x2 %0, %1, %2, %0;" : "+l"(acc[i][j]) : "l"(a2[i]), "l"(bv[j]));
    }

    float w = (stage==1 || stage==2) ? 2.f : 1.f;
    float s[8] = {0,0,0,0,0,0,0,0};
    #pragma unroll
    for (int jp=0;jp<8;jp++){
        int colL = c0 + tx*16 + jp*2;
        float b0 = gbout[colL], b1 = gbout[colL+1];
        int j0 = colL & 63;
        #pragma unroll
        for (int ii=0;ii<8;ii++){
            float g0, g1;
            asm("mov.b64 {%0, %1}, %2;" : "=f"(g0), "=f"(g1) : "l"(acc[ii][jp]));
            g0 = fast_tanh(g0 + b0);
            g1 = fast_tanh(g1 + b1);
            int rowL = ty*8 + ii;
            s[ii] = fmaf(g0, Dhs[rowL*65 + j0],     s[ii]);
            s[ii] = fmaf(g1, Dhs[rowL*65 + j0 + 1], s[ii]);
        }
    }
    int ig = tx >> 2, sub = tx & 3;
    #pragma unroll
    for (int ii=0;ii<8;ii++)
        red[(((ty*8+ii)*4 + ig)*4) + sub] = s[ii];
    __syncthreads();
    for (int u=tid; u<512; u+=256){
        float v = red[u*4] + red[u*4+1] + red[u*4+2] + red[u*4+3];
        int rowL = u >> 2, ig2 = u & 3;
        int r = r0 + rowL;
        if (r < Rr){
            int iG = blockIdx.y*4 + ig2;
            size_t o = (size_t)r*64 + iG;
            d_kz[o] = v;
            d_accz[o] += w*v;
        }
    }
}

__global__ void k_update(const float* __restrict__ times, int step){
    int idx = blockIdx.x*256 + threadIdx.x;
    if (idx >= Rr*64) return;
    float dt = times[step+1] - times[step];
    float sc = dt * (1.f/6.f);
    d_h[idx] += sc * d_acch[idx];
    d_z[idx] += sc * d_accz[idx];
    d_acch[idx] = 0.f;
    d_accz[idx] = 0.f;
}

__global__ void k_out(const float* __restrict__ convW, const float* __restrict__ convb,
                      float* __restrict__ out){
    __shared__ float szr[64];
    int r = blockIdx.x, t = threadIdx.x;
    szr[t] = d_z[(size_t)r*64 + t];
    __syncthreads();
    if (t < 12){
        float acc = convb[t];
        #pragma unroll 8
        for (int h=0; h<64; h++) acc = fmaf(szr[h], convW[t*64+h], acc);
        int b = r / Nn, n = r - b*Nn;
        out[(size_t)(b*12 + t)*Nn + n] = acc;
    }
}

// ---------------- launcher ----------------
extern "C" void kernel_launch(void* const* d_in, const int* in_sizes, int n_in,
                              void* d_out, int out_size){
    const float* coeff_a = (const float*)d_in[0];
    const float* coeff_b = (const float*)d_in[1];
    const float* coeff_c = (const float*)d_in[2];
    const float* coeff_d = (const float*)d_in[3];
    const float* times   = (const float*)d_in[4];
    const float* h_W     = (const float*)d_in[5];
    const float* h_b     = (const float*)d_in[6];
    const float* z_W     = (const float*)d_in[7];
    const float* z_b     = (const float*)d_in[8];
    const float* f_W_in  = (const float*)d_in[9];
    const float* f_b_in  = (const float*)d_in[10];
    const float* f_W_mid = (const float*)d_in[11];
    const float* f_b_mid = (const float*)d_in[12];
    const float* f_W_out = (const float*)d_in[13];
    const float* f_b_out = (const float*)d_in[14];
    const float* g_W_in  = (const float*)d_in[15];
    const float* g_b_in  = (const float*)d_in[16];
    const float* g_E     = (const float*)d_in[17];
    const float* g_Wpool = (const float*)d_in[18];
    const float* g_bpool = (const float*)d_in[19];
    const float* g_W_out = (const float*)d_in[20];
    const float* g_b_out = (const float*)d_in[21];
    const float* conv_W  = (const float*)d_in[22];
    const float* conv_b  = (const float*)d_in[23];
    float* out = (float*)d_out;

    cudaFuncSetAttribute(k_agg, cudaFuncAttributeMaxDynamicSharedMemorySize, AGG_SMEM);
    cudaFuncSetAttribute(k_gz,  cudaFuncAttributeMaxDynamicSharedMemorySize, GZ_SMEM);

    // precompute
    k_A<<<Nn, 128>>>(g_E);
    k_agcW<<<(Nn*8192 + 255)/256, 256>>>(g_E, g_Wpool);
    k_agcb<<<(Nn*64 + 255)/256, 256>>>(g_E, g_bpool);
    k_init<<<(Rr*64 + 255)/256, 256>>>(coeff_a, h_W, h_b, z_W, z_b);

    for (int step = 0; step < NSTEP; step++){
        for (int stage = 0; stage < 4; stage++){
            k_fg1<<<Rr, 64>>>(times, coeff_b, coeff_c, coeff_d,
                              f_W_in, f_b_in, f_W_mid, f_b_mid, f_W_out, f_b_out,
                              g_W_in, g_b_in, step, stage);
            k_agg<<<dim3(8,16), 256, AGG_SMEM>>>();
            k_x2<<<Nn, 256>>>();
            k_gz<<<dim3(39,16), 256, GZ_SMEM>>>(g_W_out, g_b_out, times, step, stage);
        }
        k_update<<<(Rr*64 + 255)/256, 256>>>(times, step);
    }
    k_out<<<Rr, 64>>>(conv_W, conv_b, out);
}

// round 2
// speedup vs baseline: 1.2699x; 1.2699x over previous
#include <cuda_runtime.h>
#include <cstdint>
#include <cstddef>

#define Bb 16
#define Nn 307
#define NSTEP 11
#define Rr (Bb*Nn)   // 4912

// ---------------- device scratch (no allocation allowed) ----------------
__device__ float d_A[Nn*Nn];
__device__ float d_agcW[(size_t)Nn*2*64*64];   // [n][k][i][o]
__device__ float d_agcb[Nn*64];
__device__ float d_h[Rr*64];
__device__ float d_z[Rr*64];
__device__ float d_kh[Rr*64];
__device__ float d_kz[Rr*64];
__device__ float d_acch[Rr*64];
__device__ float d_accz[Rr*64];
__device__ float d_x1g[Rr*64];
__device__ float d_y[Rr*64];
__device__ float d_x2[Rr*64];

__device__ __forceinline__ float fast_tanh(float x){
    return 1.f - __fdividef(2.f, __expf(2.f*x) + 1.f);
}

// ---------------- precompute kernels ----------------
__global__ void k_A(const float* __restrict__ gE){
    __shared__ float s[Nn];
    __shared__ float red[128];
    int n = blockIdx.x, tid = threadIdx.x;
    float en[8];
    #pragma unroll
    for (int d=0; d<8; d++) en[d] = gE[n*8+d];
    for (int m=tid; m<Nn; m+=128){
        float acc = 0.f;
        #pragma unroll
        for (int d=0; d<8; d++) acc += en[d]*gE[m*8+d];
        s[m] = fmaxf(acc, 0.f);
    }
    __syncthreads();
    float mx = -1e30f;
    for (int m=tid; m<Nn; m+=128) mx = fmaxf(mx, s[m]);
    red[tid] = mx; __syncthreads();
    for (int o=64;o>0;o>>=1){ if (tid<o) red[tid]=fmaxf(red[tid],red[tid+o]); __syncthreads(); }
    mx = red[0]; __syncthreads();
    float sum = 0.f;
    for (int m=tid; m<Nn; m+=128){ float e = expf(s[m]-mx); s[m]=e; sum+=e; }
    red[tid]=sum; __syncthreads();
    for (int o=64;o>0;o>>=1){ if (tid<o) red[tid]+=red[tid+o]; __syncthreads(); }
    float inv = 1.f/red[0];
    for (int m=tid; m<Nn; m+=128) d_A[(size_t)n*Nn+m] = s[m]*inv;
}

__global__ void k_agcW(const float* __restrict__ gE, const float* __restrict__ gWpool){
    int idx = blockIdx.x*256 + threadIdx.x;
    if (idx >= Nn*8192) return;
    int n = idx >> 13;
    int rest = idx & 8191;
    float acc = 0.f;
    #pragma unroll
    for (int d=0; d<8; d++) acc += gE[n*8+d]*gWpool[(size_t)d*8192 + rest];
    d_agcW[idx] = acc;
}

__global__ void k_agcb(const float* __restrict__ gE, const float* __restrict__ gbpool){
    int idx = blockIdx.x*256 + threadIdx.x;
    if (idx >= Nn*64) return;
    int n = idx >> 6, o = idx & 63;
    float acc = 0.f;
    #pragma unroll
    for (int d=0; d<8; d++) acc += gE[n*8+d]*gbpool[d*64+o];
    d_agcb[idx] = acc;
}

__global__ void k_init(const float* __restrict__ coeff_a,
                       const float* __restrict__ hW, const float* __restrict__ hb,
                       const float* __restrict__ zW, const float* __restrict__ zb){
    int idx = blockIdx.x*256 + threadIdx.x;
    if (idx >= Rr*64) return;
    int r = idx >> 6, h = idx & 63;
    float x0 = coeff_a[(size_t)r*(NSTEP*2) + 0];
    float x1 = coeff_a[(size_t)r*(NSTEP*2) + 1];
    d_h[idx] = x0*hW[h] + x1*hW[64+h] + hb[h];
    d_z[idx] = x0*zW[h] + x1*zW[64+h] + zb[h];
    d_acch[idx] = 0.f;
    d_accz[idx] = 0.f;
}

// ---------------- per-stage kernels ----------------
// 8 rows per 64-thread block: weight LDGs amortized over 8 rows.
__global__ void __launch_bounds__(64) k_fg1(
                      const float* __restrict__ times,
                      const float* __restrict__ cb, const float* __restrict__ cc, const float* __restrict__ cd,
                      const float* __restrict__ fWin, const float* __restrict__ fbin,
                      const float* __restrict__ fWmid, const float* __restrict__ fbmid,
                      const float* __restrict__ fWout, const float* __restrict__ fbout,
                      const float* __restrict__ gWin, const float* __restrict__ gbin,
                      int step, int stage){
    int t = threadIdx.x;
    int r0 = blockIdx.x * 8;
    __shared__ float sh[8*64], sz[8*64], sx[8*64];

    float t0 = times[step], t1 = times[step+1];
    float dt = t1 - t0;
    float c  = (stage==0) ? 0.f : ((stage==3) ? dt : 0.5f*dt);
    float tv = (stage==0) ? t0  : ((stage==3) ? t1 : (t0 + 0.5f*dt));
    float w  = (stage==1 || stage==2) ? 2.f : 1.f;

    #pragma unroll
    for (int j=0;j<8;j++){
        size_t base = (size_t)(r0+j)*64 + t;
        float hv = d_h[base], zv = d_z[base];
        if (stage){ hv += c*d_kh[base]; zv += c*d_kz[base]; }
        sh[j*64+t] = hv; sz[j*64+t] = zv;
    }
    __syncthreads();

    float af[8], ag[8];
    float bf = fbin[t], bg = gbin[t];
    #pragma unroll
    for (int j=0;j<8;j++){ af[j]=bf; ag[j]=bg; }
    #pragma unroll 8
    for (int i=0;i<64;i++){
        float wf = fWin[i*64+t];
        float wg = gWin[i*64+t];
        #pragma unroll
        for (int j=0;j<8;j++){
            af[j] = fmaf(sh[j*64+i], wf, af[j]);
            ag[j] = fmaf(sz[j*64+i], wg, ag[j]);
        }
    }
    #pragma unroll
    for (int j=0;j<8;j++)
        d_x1g[(size_t)(r0+j)*64 + t] = fmaxf(ag[j], 0.f);
    #pragma unroll
    for (int j=0;j<8;j++) sx[j*64+t] = fmaxf(af[j], 0.f);
    __syncthreads();

    float bm = fbmid[t];
    #pragma unroll
    for (int j=0;j<8;j++) af[j]=bm;
    #pragma unroll 8
    for (int i=0;i<64;i++){
        float wf = fWmid[i*64+t];
        #pragma unroll
        for (int j=0;j<8;j++) af[j] = fmaf(sx[j*64+i], wf, af[j]);
    }
    __syncthreads();
    #pragma unroll
    for (int j=0;j<8;j++) sz[j*64+t] = fmaxf(af[j], 0.f);   // reuse sz as x2 buffer
    __syncthreads();

    float2 b3 = ((const float2*)fbout)[t];
    float2 a3[8];
    #pragma unroll
    for (int j=0;j<8;j++) a3[j]=b3;
    #pragma unroll 8
    for (int i=0;i<64;i++){
        float2 wv = ((const float2*)fWout)[i*64 + t];
        #pragma unroll
        for (int j=0;j<8;j++){
            a3[j].x = fmaf(sz[j*64+i], wv.x, a3[j].x);
            a3[j].y = fmaf(sz[j*64+i], wv.y, a3[j].y);
        }
    }

    // spline derivative
    int idx = 0;
    #pragma unroll
    for (int jj=1; jj<=NSTEP-1; jj++) if (times[jj] <= tv) idx = jj;
    float frac = tv - times[idx];
    #pragma unroll
    for (int j=0;j<8;j++){
        size_t cbase = ((size_t)(r0+j)*NSTEP + idx)*2;
        float dX0 = cb[cbase]   + (cc[cbase]   + cd[cbase]  *frac)*frac;
        float dX1 = cb[cbase+1] + (cc[cbase+1] + cd[cbase+1]*frac)*frac;
        float dh = fast_tanh(a3[j].x)*dX0 + fast_tanh(a3[j].y)*dX1;
        size_t base = (size_t)(r0+j)*64 + t;
        d_kh[base] = dh;
        d_acch[base] += w*dh;
    }
}

// graph aggregation: y[b,n,:] = sum_m A[n,m] * x1g[b,m,:]
#define AGG_SMEM (Nn*64*4)
__global__ void k_agg(){
    extern __shared__ float xs[];
    int b = blockIdx.y, ch = blockIdx.x;
    int tid = threadIdx.x;
    const float* src = &d_x1g[(size_t)b*Nn*64];
    for (int i=tid; i<Nn*64; i+=256) xs[i] = src[i];
    __syncthreads();
    int t = tid & 63, rg = tid >> 6;
    int n0 = ch*39;
    int n1 = n0 + 39; if (n1 > Nn) n1 = Nn;
    for (int n = n0 + rg; n < n1; n += 4){
        const float* Arow = &d_A[(size_t)n*Nn];
        float acc = 0.f;
        int m = 0;
        #pragma unroll 4
        for (; m+4 <= Nn; m += 4){
            acc = fmaf(Arow[m],   xs[(m)*64+t],   acc);
            acc = fmaf(Arow[m+1], xs[(m+1)*64+t], acc);
            acc = fmaf(Arow[m+2], xs[(m+2)*64+t], acc);
            acc = fmaf(Arow[m+3], xs[(m+3)*64+t], acc);
        }
        for (; m<Nn; m++) acc = fmaf(Arow[m], xs[m*64+t], acc);
        d_y[((size_t)b*Nn + n)*64 + t] = acc;
    }
}

// AGC per node
__global__ void k_x2(){
    __shared__ float sx[16*64], sy[16*64];
    int n = blockIdx.x, tid = threadIdx.x;
    for (int u=tid; u<16*64; u+=256){
        int b = u >> 6, i = u & 63;
        size_t g = ((size_t)b*Nn + n)*64 + i;
        sx[u] = d_x1g[g];
        sy[u] = d_y[g];
    }
    __syncthreads();
    int o = tid & 63, bg = tid >> 6;
    const float* W0 = &d_agcW[(size_t)n*8192];
    const float* W1 = W0 + 4096;
    float bias = d_agcb[n*64+o];
    float acc[4] = {bias, bias, bias, bias};
    #pragma unroll 4
    for (int i=0;i<64;i++){
        float w0 = W0[i*64+o];
        float w1 = W1[i*64+o];
        #pragma unroll
        for (int j=0;j<4;j++){
            int b = bg*4 + j;
            acc[j] = fmaf(sx[b*64+i], w0, acc[j]);
            acc[j] = fmaf(sy[b*64+i], w1, acc[j]);
        }
    }
    #pragma unroll
    for (int j=0;j<4;j++){
        int b = bg*4 + j;
        d_x2[((size_t)b*Nn + n)*64 + o] = fmaxf(acc[j], 0.f);
    }
}

// big fused kernel: G = x2 @ g_W_out + b ; dz[r,i] = sum_j tanh(G[r,i*64+j]) * dh[r,j]
// 512 threads, 128x256 tile, conflict-free B loads, shuffle reduction.
#define GZ_XSTRIDE 132
#define GZ_XS   (64*GZ_XSTRIDE)
#define GZ_WS   (64*256)
#define GZ_SMEM ((GZ_XS + GZ_WS + 256)*4)

__global__ void __launch_bounds__(512) k_gz(
                     const float* __restrict__ gWout, const float* __restrict__ gbout,
                     int stage){
    extern __shared__ float sm[];
    float* Xs = sm;                 // [k][row], stride 132
    float* Ws = Xs + GZ_XS;         // [k][col], stride 256
    float* sb = Ws + GZ_WS;         // bias tile [256]
    int tid = threadIdx.x;
    int r0 = blockIdx.x * 128;
    int c0 = blockIdx.y * 256;

    // fill X (transposed), W, bias
    #pragma unroll
    for (int it=0; it<16; it++){
        int u = it*512 + tid;              // 8192 = 128x64
        int row = u >> 6, k = u & 63;
        int r = r0 + row;
        Xs[k*GZ_XSTRIDE + row] = (r < Rr) ? d_x2[(size_t)r*64 + k] : 0.f;
    }
    #pragma unroll
    for (int it=0; it<32; it++){
        int u = it*512 + tid;              // 16384 = 64x256
        int k = u >> 8, cc2 = u & 255;
        Ws[u] = gWout[(size_t)k*4096 + c0 + cc2];
    }
    if (tid < 256) sb[tid] = gbout[c0 + tid];
    __syncthreads();

    int tx = tid & 31, ty = tid >> 5;      // ty uniform within warp
    unsigned long long acc[8][4];
    #pragma unroll
    for (int i=0;i<8;i++)
        #pragma unroll
        for (int p=0;p<4;p++) acc[i][p] = 0ull;

    const float* Xbase = &Xs[ty*8];
    #pragma unroll 4
    for (int k=0;k<64;k++){
        float4 aLo = *(const float4*)&Xbase[k*GZ_XSTRIDE];
        float4 aHi = *(const float4*)&Xbase[k*GZ_XSTRIDE + 4];
        float4 bA  = *(const float4*)&Ws[k*256 + tx*4];
        float4 bB  = *(const float4*)&Ws[k*256 + 128 + tx*4];
        unsigned long long b0,b1,b2,b3;
        asm("mov.b64 %0,{%1,%2};" : "=l"(b0) : "f"(bA.x), "f"(bA.y));
        asm("mov.b64 %0,{%1,%2};" : "=l"(b1) : "f"(bA.z), "f"(bA.w));
        asm("mov.b64 %0,{%1,%2};" : "=l"(b2) : "f"(bB.x), "f"(bB.y));
        asm("mov.b64 %0,{%1,%2};" : "=l"(b3) : "f"(bB.z), "f"(bB.w));
        float av[8] = {aLo.x,aLo.y,aLo.z,aLo.w,aHi.x,aHi.y,aHi.z,aHi.w};
        #pragma unroll
        for (int i=0;i<8;i++){
            unsigned long long a2;
            asm("mov.b64 %0,{%1,%1};" : "=l"(a2) : "f"(av[i]));
            asm("fma.rn.f32x2 %0, %1, %2, %0;" : "+l"(acc[i][0]) : "l"(a2), "l"(b0));
            asm("fma.rn.f32x2 %0, %1, %2, %0;" : "+l"(acc[i][1]) : "l"(a2), "l"(b1));
            asm("fma.rn.f32x2 %0, %1, %2, %0;" : "+l"(acc[i][2]) : "l"(a2), "l"(b2));
            asm("fma.rn.f32x2 %0, %1, %2, %0;" : "+l"(acc[i][3]) : "l"(a2), "l"(b3));
        }
    }

    // epilogue: bias + tanh + contract with dh, reduce over 16-lane halves
    float w = (stage==1 || stage==2) ? 2.f : 1.f;
    int jb = (4*tx) & 63;
    float bA0 = sb[4*tx],       bA1 = sb[4*tx+1];
    float bA2 = sb[4*tx+2],     bA3 = sb[4*tx+3];
    float bB0 = sb[128+4*tx],   bB1 = sb[128+4*tx+1];
    float bB2 = sb[128+4*tx+2], bB3 = sb[128+4*tx+3];
    float sA[8], sB[8];
    #pragma unroll
    for (int i=0;i<8;i++){
        int r = r0 + ty*8 + i;
        float4 dhv = make_float4(0.f,0.f,0.f,0.f);
        if (r < Rr) dhv = *(const float4*)&d_kh[(size_t)r*64 + jb];
        float g0,g1;
        asm("mov.b64 {%0,%1},%2;" : "=f"(g0), "=f"(g1) : "l"(acc[i][0]));
        float s = fast_tanh(g0+bA0)*dhv.x + fast_tanh(g1+bA1)*dhv.y;
        asm("mov.b64 {%0,%1},%2;" : "=f"(g0), "=f"(g1) : "l"(acc[i][1]));
        s += fast_tanh(g0+bA2)*dhv.z + fast_tanh(g1+bA3)*dhv.w;
        sA[i] = s;
        asm("mov.b64 {%0,%1},%2;" : "=f"(g0), "=f"(g1) : "l"(acc[i][2]));
        s = fast_tanh(g0+bB0)*dhv.x + fast_tanh(g1+bB1)*dhv.y;
        asm("mov.b64 {%0,%1},%2;" : "=f"(g0), "=f"(g1) : "l"(acc[i][3]));
        s += fast_tanh(g0+bB2)*dhv.z + fast_tanh(g1+bB3)*dhv.w;
        sB[i] = s;
    }
    #pragma unroll
    for (int s2=1; s2<16; s2<<=1){
        #pragma unroll
        for (int i=0;i<8;i++){
            sA[i] += __shfl_xor_sync(0xffffffffu, sA[i], s2);
            sB[i] += __shfl_xor_sync(0xffffffffu, sB[i], s2);
        }
    }
    if (tx == 0 || tx == 16){
        int ihalf = (tx == 16) ? 1 : 0;
        int iA = blockIdx.y*4 + ihalf;
        int iB = iA + 2;
        #pragma unroll
        for (int i=0;i<8;i++){
            int r = r0 + ty*8 + i;
            if (r < Rr){
                size_t oA = (size_t)r*64 + iA;
                size_t oB = (size_t)r*64 + iB;
                d_kz[oA] = sA[i];
                d_kz[oB] = sB[i];
                d_accz[oA] += w*sA[i];
                d_accz[oB] += w*sB[i];
            }
        }
    }
}

__global__ void k_update(const float* __restrict__ times, int step){
    int idx = blockIdx.x*256 + threadIdx.x;
    if (idx >= Rr*64) return;
    float dt = times[step+1] - times[step];
    float sc = dt * (1.f/6.f);
    d_h[idx] += sc * d_acch[idx];
    d_z[idx] += sc * d_accz[idx];
    d_acch[idx] = 0.f;
    d_accz[idx] = 0.f;
}

__global__ void k_out(const float* __restrict__ convW, const float* __restrict__ convb,
                      float* __restrict__ out){
    __shared__ float szr[64];
    int r = blockIdx.x, t = threadIdx.x;
    szr[t] = d_z[(size_t)r*64 + t];
    __syncthreads();
    if (t < 12){
        float acc = convb[t];
        #pragma unroll 8
        for (int h=0; h<64; h++) acc = fmaf(szr[h], convW[t*64+h], acc);
        int b = r / Nn, n = r - b*Nn;
        out[(size_t)(b*12 + t)*Nn + n] = acc;
    }
}

// ---------------- launcher ----------------
extern "C" void kernel_launch(void* const* d_in, const int* in_sizes, int n_in,
                              void* d_out, int out_size){
    const float* coeff_a = (const float*)d_in[0];
    const float* coeff_b = (const float*)d_in[1];
    const float* coeff_c = (const float*)d_in[2];
    const float* coeff_d = (const float*)d_in[3];
    const float* times   = (const float*)d_in[4];
    const float* h_W     = (const float*)d_in[5];
    const float* h_b     = (const float*)d_in[6];
    const float* z_W     = (const float*)d_in[7];
    const float* z_b     = (const float*)d_in[8];
    const float* f_W_in  = (const float*)d_in[9];
    const float* f_b_in  = (const float*)d_in[10];
    const float* f_W_mid = (const float*)d_in[11];
    const float* f_b_mid = (const float*)d_in[12];
    const float* f_W_out = (const float*)d_in[13];
    const float* f_b_out = (const float*)d_in[14];
    const float* g_W_in  = (const float*)d_in[15];
    const float* g_b_in  = (const float*)d_in[16];
    const float* g_E     = (const float*)d_in[17];
    const float* g_Wpool = (const float*)d_in[18];
    const float* g_bpool = (const float*)d_in[19];
    const float* g_W_out = (const float*)d_in[20];
    const float* g_b_out = (const float*)d_in[21];
    const float* conv_W  = (const float*)d_in[22];
    const float* conv_b  = (const float*)d_in[23];
    float* out = (float*)d_out;

    cudaFuncSetAttribute(k_agg, cudaFuncAttributeMaxDynamicSharedMemorySize, AGG_SMEM);
    cudaFuncSetAttribute(k_gz,  cudaFuncAttributeMaxDynamicSharedMemorySize, GZ_SMEM);

    k_A<<<Nn, 128>>>(g_E);
    k_agcW<<<(Nn*8192 + 255)/256, 256>>>(g_E, g_Wpool);
    k_agcb<<<(Nn*64 + 255)/256, 256>>>(g_E, g_bpool);
    k_init<<<(Rr*64 + 255)/256, 256>>>(coeff_a, h_W, h_b, z_W, z_b);

    for (int step = 0; step < NSTEP; step++){
        for (int stage = 0; stage < 4; stage++){
            k_fg1<<<Rr/8, 64>>>(times, coeff_b, coeff_c, coeff_d,
                                f_W_in, f_b_in, f_W_mid, f_b_mid, f_W_out, f_b_out,
                                g_W_in, g_b_in, step, stage);
            k_agg<<<dim3(8,16), 256, AGG_SMEM>>>();
            k_x2<<<Nn, 256>>>();
            k_gz<<<dim3(39,16), 512, GZ_SMEM>>>(g_W_out, g_b_out, stage);
        }
        k_update<<<(Rr*64 + 255)/256, 256>>>(times, step);
    }
    k_out<<<Rr, 64>>>(conv_W, conv_b, out);
}

// round 3
// speedup vs baseline: 1.3597x; 1.0707x over previous
#include <cuda_runtime.h>
#include <cstdint>
#include <cstddef>

#define Bb 16
#define Nn 307
#define NSTEP 11
#define Rr (Bb*Nn)   // 4912
#define APAD 308
typedef unsigned long long ull;

// ---------------- device scratch ----------------
__device__ float d_A[Nn*APAD];
__device__ float d_agcW[(size_t)Nn*2*64*64];
__device__ float d_agcb[Nn*64];
__device__ float d_h[Rr*64];
__device__ float d_z[Rr*64];
__device__ float d_kh[Rr*64];
__device__ float d_kz[Rr*64];
__device__ float d_acch[Rr*64];
__device__ float d_accz[Rr*64];
__device__ float d_x1g[Rr*64];
__device__ float d_y[Rr*64];
__device__ float d_x2[Rr*64];

__device__ __forceinline__ float fast_tanh(float x){
    return 1.f - __fdividef(2.f, __expf(2.f*x) + 1.f);
}

// ---------------- precompute: pre1 = softmax A + agc bias ----------------
__global__ void k_pre1(const float* __restrict__ gE, const float* __restrict__ gbpool){
    int tid = threadIdx.x;
    if (blockIdx.x < Nn){
        // adjacency row n: softmax(relu(gE[n] . gE[m]))
        __shared__ float s[Nn];
        __shared__ float red[256];
        int n = blockIdx.x;
        float en[8];
        #pragma unroll
        for (int d=0; d<8; d++) en[d] = gE[n*8+d];
        for (int m=tid; m<Nn; m+=256){
            float acc = 0.f;
            #pragma unroll
            for (int d=0; d<8; d++) acc += en[d]*gE[m*8+d];
            s[m] = fmaxf(acc, 0.f);
        }
        __syncthreads();
        float mx = -1e30f;
        for (int m=tid; m<Nn; m+=256) mx = fmaxf(mx, s[m]);
        red[tid] = mx; __syncthreads();
        for (int o=128;o>0;o>>=1){ if (tid<o) red[tid]=fmaxf(red[tid],red[tid+o]); __syncthreads(); }
        mx = red[0]; __syncthreads();
        float sum = 0.f;
        for (int m=tid; m<Nn; m+=256){ float e = expf(s[m]-mx); s[m]=e; sum+=e; }
        red[tid]=sum; __syncthreads();
        for (int o=128;o>0;o>>=1){ if (tid<o) red[tid]+=red[tid+o]; __syncthreads(); }
        float inv = 1.f/red[0];
        for (int m=tid; m<Nn; m+=256) d_A[(size_t)n*APAD+m] = s[m]*inv;
        if (tid == 0) d_A[(size_t)n*APAD + Nn] = 0.f;   // pad col
    } else {
        int idx = (blockIdx.x - Nn)*256 + tid;
        if (idx < Nn*64){
            int n = idx >> 6, o = idx & 63;
            float acc = 0.f;
            #pragma unroll
            for (int d=0; d<8; d++) acc += gE[n*8+d]*gbpool[d*64+o];
            d_agcb[idx] = acc;
        }
    }
}

// pre2 = agc weights
__global__ void k_pre2(const float* __restrict__ gE, const float* __restrict__ gWpool){
    int idx = blockIdx.x*256 + threadIdx.x;
    if (idx >= Nn*8192) return;
    int n = idx >> 13;
    int rest = idx & 8191;
    float acc = 0.f;
    #pragma unroll
    for (int d=0; d<8; d++) acc += gE[n*8+d]*gWpool[(size_t)d*8192 + rest];
    d_agcW[idx] = acc;
}

// ---------------- per-stage kernels ----------------
// 8 rows per 64-thread block. Handles state init (step0), RK4 update fold (stage0),
// f-MLP chain -> kh, g layer1 -> x1g.
__global__ void __launch_bounds__(64) k_fg1(
                      const float* __restrict__ times,
                      const float* __restrict__ coeff_a,
                      const float* __restrict__ cb, const float* __restrict__ cc, const float* __restrict__ cd,
                      const float* __restrict__ hW, const float* __restrict__ hb,
                      const float* __restrict__ zW, const float* __restrict__ zb,
                      const float* __restrict__ fWin, const float* __restrict__ fbin,
                      const float* __restrict__ fWmid, const float* __restrict__ fbmid,
                      const float* __restrict__ fWout, const float* __restrict__ fbout,
                      const float* __restrict__ gWin, const float* __restrict__ gbin,
                      int step, int stage){
    int t = threadIdx.x;
    int r0 = blockIdx.x * 8;
    __shared__ float sh[8*64], sz[8*64], sx[8*64];

    float t0 = times[step], t1 = times[step+1];
    float dt = t1 - t0;
    float c  = (stage==0) ? 0.f : ((stage==3) ? dt : 0.5f*dt);
    float tv = (stage==0) ? t0  : ((stage==3) ? t1 : (t0 + 0.5f*dt));
    float w  = (stage==1 || stage==2) ? 2.f : 1.f;

    if (stage == 0){
        if (step == 0){
            float wh0 = hW[t], wh1 = hW[64+t], bh = hb[t];
            float wz0 = zW[t], wz1 = zW[64+t], bz = zb[t];
            #pragma unroll
            for (int j=0;j<8;j++){
                int r = r0+j;
                float x0 = coeff_a[(size_t)r*(NSTEP*2) + 0];
                float x1 = coeff_a[(size_t)r*(NSTEP*2) + 1];
                float hv = x0*wh0 + x1*wh1 + bh;
                float zv = x0*wz0 + x1*wz1 + bz;
                size_t base = (size_t)r*64 + t;
                d_h[base] = hv; d_z[base] = zv;
                sh[j*64+t] = hv; sz[j*64+t] = zv;
            }
        } else {
            float scp = (times[step] - times[step-1]) * (1.f/6.f);
            #pragma unroll
            for (int j=0;j<8;j++){
                size_t base = (size_t)(r0+j)*64 + t;
                float hv = d_h[base] + scp*d_acch[base];
                float zv = d_z[base] + scp*d_accz[base];
                d_h[base] = hv; d_z[base] = zv;
                sh[j*64+t] = hv; sz[j*64+t] = zv;
            }
        }
    } else {
        #pragma unroll
        for (int j=0;j<8;j++){
            size_t base = (size_t)(r0+j)*64 + t;
            sh[j*64+t] = d_h[base] + c*d_kh[base];
            sz[j*64+t] = d_z[base] + c*d_kz[base];
        }
    }
    __syncthreads();

    float af[8], ag[8];
    float bf = fbin[t], bg = gbin[t];
    #pragma unroll
    for (int j=0;j<8;j++){ af[j]=bf; ag[j]=bg; }
    #pragma unroll 8
    for (int i=0;i<64;i++){
        float wf = fWin[i*64+t];
        float wg = gWin[i*64+t];
        #pragma unroll
        for (int j=0;j<8;j++){
            af[j] = fmaf(sh[j*64+i], wf, af[j]);
            ag[j] = fmaf(sz[j*64+i], wg, ag[j]);
        }
    }
    #pragma unroll
    for (int j=0;j<8;j++)
        d_x1g[(size_t)(r0+j)*64 + t] = fmaxf(ag[j], 0.f);
    #pragma unroll
    for (int j=0;j<8;j++) sx[j*64+t] = fmaxf(af[j], 0.f);
    __syncthreads();

    float bm = fbmid[t];
    #pragma unroll
    for (int j=0;j<8;j++) af[j]=bm;
    #pragma unroll 8
    for (int i=0;i<64;i++){
        float wf = fWmid[i*64+t];
        #pragma unroll
        for (int j=0;j<8;j++) af[j] = fmaf(sx[j*64+i], wf, af[j]);
    }
    __syncthreads();
    #pragma unroll
    for (int j=0;j<8;j++) sz[j*64+t] = fmaxf(af[j], 0.f);   // reuse sz
    __syncthreads();

    float2 b3 = ((const float2*)fbout)[t];
    float2 a3[8];
    #pragma unroll
    for (int j=0;j<8;j++) a3[j]=b3;
    #pragma unroll 8
    for (int i=0;i<64;i++){
        float2 wv = ((const float2*)fWout)[i*64 + t];
        #pragma unroll
        for (int j=0;j<8;j++){
            a3[j].x = fmaf(sz[j*64+i], wv.x, a3[j].x);
            a3[j].y = fmaf(sz[j*64+i], wv.y, a3[j].y);
        }
    }

    int idx = 0;
    #pragma unroll
    for (int jj=1; jj<=NSTEP-1; jj++) if (times[jj] <= tv) idx = jj;
    float frac = tv - times[idx];
    #pragma unroll
    for (int j=0;j<8;j++){
        size_t cbase = ((size_t)(r0+j)*NSTEP + idx)*2;
        float dX0 = cb[cbase]   + (cc[cbase]   + cd[cbase]  *frac)*frac;
        float dX1 = cb[cbase+1] + (cc[cbase+1] + cd[cbase+1]*frac)*frac;
        float dh = fast_tanh(a3[j].x)*dX0 + fast_tanh(a3[j].y)*dX1;
        size_t base = (size_t)(r0+j)*64 + t;
        d_kh[base] = dh;
        d_acch[base] = (stage==0) ? dh : (d_acch[base] + w*dh);
    }
}

// graph aggregation: y[b,n,:] = sum_m A[n,m] * x1g[b,m,:]
// float4 A loads (lane-uniform), 2 nodes per thread, 2 partial accumulators.
#define AGG_SMEM (APAD*64*4)
__global__ void __launch_bounds__(256) k_agg(){
    extern __shared__ float xs[];           // [308][64], row 307 zero
    int b = blockIdx.y, ch = blockIdx.x;
    int tid = threadIdx.x;
    const float* src = &d_x1g[(size_t)b*Nn*64];
    for (int i=tid; i<APAD*64; i+=256) xs[i] = (i < Nn*64) ? src[i] : 0.f;
    __syncthreads();
    int t = tid & 63, rg = tid >> 6;        // 4 groups
    int n0 = ch*39;
    int n1 = n0 + 39; if (n1 > Nn) n1 = Nn;
    for (int n = n0 + rg; n < n1; n += 8){
        int nB = n + 4;
        bool hasB = (nB < n1);
        const float4* A0 = (const float4*)&d_A[(size_t)n*APAD];
        const float4* A1 = (const float4*)&d_A[(size_t)(hasB ? nB : n)*APAD];
        float a0a=0.f, a0b=0.f, a1a=0.f, a1b=0.f;
        #pragma unroll 4
        for (int m4=0; m4<APAD/4; m4++){
            float4 q0 = A0[m4];
            float4 q1 = A1[m4];
            int mb = m4*4;
            float x0 = xs[(mb  )*64+t];
            float x1 = xs[(mb+1)*64+t];
            float x2v= xs[(mb+2)*64+t];
            float x3 = xs[(mb+3)*64+t];
            a0a = fmaf(q0.x, x0, a0a); a0b = fmaf(q0.y, x1, a0b);
            a0a = fmaf(q0.z, x2v,a0a); a0b = fmaf(q0.w, x3, a0b);
            a1a = fmaf(q1.x, x0, a1a); a1b = fmaf(q1.y, x1, a1b);
            a1a = fmaf(q1.z, x2v,a1a); a1b = fmaf(q1.w, x3, a1b);
        }
        d_y[((size_t)b*Nn + n)*64 + t] = a0a + a0b;
        if (hasB) d_y[((size_t)b*Nn + nB)*64 + t] = a1a + a1b;
    }
}

// AGC per node
__global__ void __launch_bounds__(256) k_x2(){
    __shared__ float sx[16*64], sy[16*64];
    int n = blockIdx.x, tid = threadIdx.x;
    for (int u=tid; u<16*64; u+=256){
        int b = u >> 6, i = u & 63;
        size_t g = ((size_t)b*Nn + n)*64 + i;
        sx[u] = d_x1g[g];
        sy[u] = d_y[g];
    }
    __syncthreads();
    int o = tid & 63, bg = tid >> 6;
    const float* W0 = &d_agcW[(size_t)n*8192];
    const float* W1 = W0 + 4096;
    float bias = d_agcb[n*64+o];
    float acc[4] = {bias, bias, bias, bias};
    #pragma unroll 4
    for (int i=0;i<64;i++){
        float w0 = W0[i*64+o];
        float w1 = W1[i*64+o];
        #pragma unroll
        for (int j=0;j<4;j++){
            int b = bg*4 + j;
            acc[j] = fmaf(sx[b*64+i], w0, acc[j]);
            acc[j] = fmaf(sy[b*64+i], w1, acc[j]);
        }
    }
    #pragma unroll
    for (int j=0;j<4;j++){
        int b = bg*4 + j;
        d_x2[((size_t)b*Nn + n)*64 + o] = fmaxf(acc[j], 0.f);
    }
}

// big fused GEMM+tanh+contract. X pre-duplicated {x,x} in smem -> LDS.64 broadcasts.
#define GZ_X2STRIDE 130
#define GZ_SMEM ((64*GZ_X2STRIDE*2 + 64*256 + 256)*4)

__global__ void __launch_bounds__(512) k_gz(
                     const float* __restrict__ gWout, const float* __restrict__ gbout,
                     int stage){
    extern __shared__ float sm[];
    float2* Xs2 = (float2*)sm;                  // [k][row], stride 130 (float2)
    float* Ws = sm + 64*GZ_X2STRIDE*2;          // [k][256]
    float* sb = Ws + 64*256;
    int tid = threadIdx.x;
    int r0 = blockIdx.x * 128;
    int c0 = blockIdx.y * 256;

    #pragma unroll
    for (int it=0; it<4; it++){
        int u = it*512 + tid;                   // 2048 float4 loads of X
        int row = u >> 4, kq = u & 15;
        int r = r0 + row;
        float4 v = (r < Rr) ? *(const float4*)&d_x2[(size_t)r*64 + kq*4]
                            : make_float4(0.f,0.f,0.f,0.f);
        Xs2[(kq*4+0)*GZ_X2STRIDE + row] = make_float2(v.x, v.x);
        Xs2[(kq*4+1)*GZ_X2STRIDE + row] = make_float2(v.y, v.y);
        Xs2[(kq*4+2)*GZ_X2STRIDE + row] = make_float2(v.z, v.z);
        Xs2[(kq*4+3)*GZ_X2STRIDE + row] = make_float2(v.w, v.w);
    }
    #pragma unroll
    for (int it=0; it<8; it++){
        int u = it*512 + tid;                   // 4096 float4 loads of W
        int k = u >> 6, c4 = u & 63;
        *(float4*)&Ws[k*256 + c4*4] = *(const float4*)&gWout[(size_t)k*4096 + c0 + c4*4];
    }
    if (tid < 256) sb[tid] = gbout[c0 + tid];
    __syncthreads();

    int tx = tid & 31, ty = tid >> 5;
    ull acc[8][4];
    #pragma unroll
    for (int i=0;i<8;i++)
        #pragma unroll
        for (int p=0;p<4;p++) acc[i][p] = 0ull;

    #pragma unroll 2
    for (int k=0;k<64;k++){
        float4 bA  = *(const float4*)&Ws[k*256 + tx*4];
        float4 bB  = *(const float4*)&Ws[k*256 + 128 + tx*4];
        ull b0,b1,b2,b3;
        asm("mov.b64 %0,{%1,%2};" : "=l"(b0) : "f"(bA.x), "f"(bA.y));
        asm("mov.b64 %0,{%1,%2};" : "=l"(b1) : "f"(bA.z), "f"(bA.w));
        asm("mov.b64 %0,{%1,%2};" : "=l"(b2) : "f"(bB.x), "f"(bB.y));
        asm("mov.b64 %0,{%1,%2};" : "=l"(b3) : "f"(bB.z), "f"(bB.w));
        const ull* Xrow = (const ull*)&Xs2[k*GZ_X2STRIDE + ty*8];
        #pragma unroll
        for (int i=0;i<8;i++){
            ull a2 = Xrow[i];
            asm("fma.rn.f32x2 %0, %1, %2, %0;" : "+l"(acc[i][0]) : "l"(a2), "l"(b0));
            asm("fma.rn.f32x2 %0, %1, %2, %0;" : "+l"(acc[i][1]) : "l"(a2), "l"(b1));
            asm("fma.rn.f32x2 %0, %1, %2, %0;" : "+l"(acc[i][2]) : "l"(a2), "l"(b2));
            asm("fma.rn.f32x2 %0, %1, %2, %0;" : "+l"(acc[i][3]) : "l"(a2), "l"(b3));
        }
    }

    float w = (stage==1 || stage==2) ? 2.f : 1.f;
    int jb = (4*tx) & 63;
    float bA0 = sb[4*tx],       bA1 = sb[4*tx+1];
    float bA2 = sb[4*tx+2],     bA3 = sb[4*tx+3];
    float bB0 = sb[128+4*tx],   bB1 = sb[128+4*tx+1];
    float bB2 = sb[128+4*tx+2], bB3 = sb[128+4*tx+3];
    float sA[8], sB[8];
    #pragma unroll
    for (int i=0;i<8;i++){
        int r = r0 + ty*8 + i;
        float4 dhv = make_float4(0.f,0.f,0.f,0.f);
        if (r < Rr) dhv = *(const float4*)&d_kh[(size_t)r*64 + jb];
        float g0,g1;
        asm("mov.b64 {%0,%1},%2;" : "=f"(g0), "=f"(g1) : "l"(acc[i][0]));
        float s = fast_tanh(g0+bA0)*dhv.x + fast_tanh(g1+bA1)*dhv.y;
        asm("mov.b64 {%0,%1},%2;" : "=f"(g0), "=f"(g1) : "l"(acc[i][1]));
        s += fast_tanh(g0+bA2)*dhv.z + fast_tanh(g1+bA3)*dhv.w;
        sA[i] = s;
        asm("mov.b64 {%0,%1},%2;" : "=f"(g0), "=f"(g1) : "l"(acc[i][2]));
        s = fast_tanh(g0+bB0)*dhv.x + fast_tanh(g1+bB1)*dhv.y;
        asm("mov.b64 {%0,%1},%2;" : "=f"(g0), "=f"(g1) : "l"(acc[i][3]));
        s += fast_tanh(g0+bB2)*dhv.z + fast_tanh(g1+bB3)*dhv.w;
        sB[i] = s;
    }
    #pragma unroll
    for (int s2=1; s2<16; s2<<=1){
        #pragma unroll
        for (int i=0;i<8;i++){
            sA[i] += __shfl_xor_sync(0xffffffffu, sA[i], s2);
            sB[i] += __shfl_xor_sync(0xffffffffu, sB[i], s2);
        }
    }
    if (tx == 0 || tx == 16){
        int ihalf = (tx == 16) ? 1 : 0;
        int iA = blockIdx.y*4 + ihalf;
        int iB = iA + 2;
        #pragma unroll
        for (int i=0;i<8;i++){
            int r = r0 + ty*8 + i;
            if (r < Rr){
                size_t oA = (size_t)r*64 + iA;
                size_t oB = (size_t)r*64 + iB;
                d_kz[oA] = sA[i];
                d_kz[oB] = sB[i];
                d_accz[oA] = (stage==0) ? sA[i] : (d_accz[oA] + w*sA[i]);
                d_accz[oB] = (stage==0) ? sB[i] : (d_accz[oB] + w*sB[i]);
            }
        }
    }
}

// output conv; applies the final RK4 update to z on the fly
__global__ void k_out(const float* __restrict__ convW, const float* __restrict__ convb,
                      const float* __restrict__ times, float* __restrict__ out){
    __shared__ float szr[64];
    int r = blockIdx.x, t = threadIdx.x;
    float sc = (times[NSTEP] - times[NSTEP-1]) * (1.f/6.f);
    size_t base = (size_t)r*64 + t;
    szr[t] = d_z[base] + sc*d_accz[base];
    __syncthreads();
    if (t < 12){
        float acc = convb[t];
        #pragma unroll 8
        for (int h=0; h<64; h++) acc = fmaf(szr[h], convW[t*64+h], acc);
        int b = r / Nn, n = r - b*Nn;
        out[(size_t)(b*12 + t)*Nn + n] = acc;
    }
}

// ---------------- launcher ----------------
extern "C" void kernel_launch(void* const* d_in, const int* in_sizes, int n_in,
                              void* d_out, int out_size){
    const float* coeff_a = (const float*)d_in[0];
    const float* coeff_b = (const float*)d_in[1];
    const float* coeff_c = (const float*)d_in[2];
    const float* coeff_d = (const float*)d_in[3];
    const float* times   = (const float*)d_in[4];
    const float* h_W     = (const float*)d_in[5];
    const float* h_b     = (const float*)d_in[6];
    const float* z_W     = (const float*)d_in[7];
    const float* z_b     = (const float*)d_in[8];
    const float* f_W_in  = (const float*)d_in[9];
    const float* f_b_in  = (const float*)d_in[10];
    const float* f_W_mid = (const float*)d_in[11];
    const float* f_b_mid = (const float*)d_in[12];
    const float* f_W_out = (const float*)d_in[13];
    const float* f_b_out = (const float*)d_in[14];
    const float* g_W_in  = (const float*)d_in[15];
    const float* g_b_in  = (const float*)d_in[16];
    const float* g_E     = (const float*)d_in[17];
    const float* g_Wpool = (const float*)d_in[18];
    const float* g_bpool = (const float*)d_in[19];
    const float* g_W_out = (const float*)d_in[20];
    const float* g_b_out = (const float*)d_in[21];
    const float* conv_W  = (const float*)d_in[22];
    const float* conv_b  = (const float*)d_in[23];
    float* out = (float*)d_out;

    cudaFuncSetAttribute(k_agg, cudaFuncAttributeMaxDynamicSharedMemorySize, AGG_SMEM);
    cudaFuncSetAttribute(k_gz,  cudaFuncAttributeMaxDynamicSharedMemorySize, GZ_SMEM);

    k_pre1<<<Nn + (Nn*64 + 255)/256, 256>>>(g_E, g_bpool);
    k_pre2<<<(Nn*8192 + 255)/256, 256>>>(g_E, g_Wpool);

    for (int step = 0; step < NSTEP; step++){
        for (int stage = 0; stage < 4; stage++){
            k_fg1<<<Rr/8, 64>>>(times, coeff_a, coeff_b, coeff_c, coeff_d,
                                h_W, h_b, z_W, z_b,
                                f_W_in, f_b_in, f_W_mid, f_b_mid, f_W_out, f_b_out,
                                g_W_in, g_b_in, step, stage);
            k_agg<<<dim3(8,16), 256, AGG_SMEM>>>();
            k_x2<<<Nn, 256>>>();
            k_gz<<<dim3(39,16), 512, GZ_SMEM>>>(g_W_out, g_b_out, stage);
        }
    }
    k_out<<<Rr, 64>>>(conv_W, conv_b, times, out);
}

// round 4
// speedup vs baseline: 1.6257x; 1.1956x over previous
#include <cuda_runtime.h>
#include <cstdint>
#include <cstddef>

#define Bb 16
#define Nn 307
#define NSTEP 11
#define Rr (Bb*Nn)   // 4912
#define AGK 320      // padded GEMM K / A stride
typedef unsigned long long ull;

// ---------------- device scratch (zero-initialized; pads never written) ----------------
__device__ float d_A[AGK*AGK];          // [320][320]; rows/cols >=307 stay 0
__device__ float d_agcW[(size_t)Nn*2*64*64];
__device__ float d_agcb[Nn*64];
__device__ float d_h[Rr*64];
__device__ float d_z[Rr*64];
__device__ float d_kh[Rr*64];
__device__ float d_kz[Rr*64];
__device__ float d_acch[Rr*64];
__device__ float d_accz[Rr*64];
__device__ float d_x1gT[(size_t)AGK*1024];  // [m][b*64+i]; rows >=307 stay 0
__device__ float d_yT[(size_t)Nn*1024];
__device__ float d_x2[Rr*64];

__device__ __forceinline__ float fast_tanh(float x){
    return 1.f - __fdividef(2.f, __expf(2.f*x) + 1.f);
}

// ---------------- fused precompute: softmax A rows + agc bias + agc weights ----------------
#define PRE_AGCB_BLKS ((Nn*64 + 255)/256)
#define PRE_AGCW_BLKS ((Nn*8192 + 255)/256)
__global__ void k_pre(const float* __restrict__ gE,
                      const float* __restrict__ gbpool,
                      const float* __restrict__ gWpool){
    int tid = threadIdx.x;
    if (blockIdx.x < Nn){
        __shared__ float s[Nn];
        __shared__ float red[256];
        int n = blockIdx.x;
        float en[8];
        #pragma unroll
        for (int d=0; d<8; d++) en[d] = gE[n*8+d];
        for (int m=tid; m<Nn; m+=256){
            float acc = 0.f;
            #pragma unroll
            for (int d=0; d<8; d++) acc += en[d]*gE[m*8+d];
            s[m] = fmaxf(acc, 0.f);
        }
        __syncthreads();
        float mx = -1e30f;
        for (int m=tid; m<Nn; m+=256) mx = fmaxf(mx, s[m]);
        red[tid] = mx; __syncthreads();
        for (int o=128;o>0;o>>=1){ if (tid<o) red[tid]=fmaxf(red[tid],red[tid+o]); __syncthreads(); }
        mx = red[0]; __syncthreads();
        float sum = 0.f;
        for (int m=tid; m<Nn; m+=256){ float e = expf(s[m]-mx); s[m]=e; sum+=e; }
        red[tid]=sum; __syncthreads();
        for (int o=128;o>0;o>>=1){ if (tid<o) red[tid]+=red[tid+o]; __syncthreads(); }
        float inv = 1.f/red[0];
        for (int m=tid; m<Nn; m+=256) d_A[(size_t)n*AGK+m] = s[m]*inv;
    } else if (blockIdx.x < Nn + PRE_AGCB_BLKS){
        int idx = (blockIdx.x - Nn)*256 + tid;
        if (idx < Nn*64){
            int n = idx >> 6, o = idx & 63;
            float acc = 0.f;
            #pragma unroll
            for (int d=0; d<8; d++) acc += gE[n*8+d]*gbpool[d*64+o];
            d_agcb[idx] = acc;
        }
    } else {
        int idx = (blockIdx.x - Nn - PRE_AGCB_BLKS)*256 + tid;
        if (idx < Nn*8192){
            int n = idx >> 13;
            int rest = idx & 8191;
            float acc = 0.f;
            #pragma unroll
            for (int d=0; d<8; d++) acc += gE[n*8+d]*gWpool[(size_t)d*8192 + rest];
            d_agcW[idx] = acc;
        }
    }
}

// ---------------- per-stage kernels ----------------
__global__ void __launch_bounds__(64) k_fg1(
                      const float* __restrict__ times,
                      const float* __restrict__ coeff_a,
                      const float* __restrict__ cb, const float* __restrict__ cc, const float* __restrict__ cd,
                      const float* __restrict__ hW, const float* __restrict__ hb,
                      const float* __restrict__ zW, const float* __restrict__ zb,
                      const float* __restrict__ fWin, const float* __restrict__ fbin,
                      const float* __restrict__ fWmid, const float* __restrict__ fbmid,
                      const float* __restrict__ fWout, const float* __restrict__ fbout,
                      const float* __restrict__ gWin, const float* __restrict__ gbin,
                      int step, int stage){
    int t = threadIdx.x;
    int r0 = blockIdx.x * 8;
    __shared__ float sh[8*64], sz[8*64], sx[8*64];

    float t0 = times[step], t1 = times[step+1];
    float dt = t1 - t0;
    float c  = (stage==0) ? 0.f : ((stage==3) ? dt : 0.5f*dt);
    float tv = (stage==0) ? t0  : ((stage==3) ? t1 : (t0 + 0.5f*dt));
    float w  = (stage==1 || stage==2) ? 2.f : 1.f;

    if (stage == 0){
        if (step == 0){
            float wh0 = hW[t], wh1 = hW[64+t], bh = hb[t];
            float wz0 = zW[t], wz1 = zW[64+t], bz = zb[t];
            #pragma unroll
            for (int j=0;j<8;j++){
                int r = r0+j;
                float x0 = coeff_a[(size_t)r*(NSTEP*2) + 0];
                float x1 = coeff_a[(size_t)r*(NSTEP*2) + 1];
                float hv = x0*wh0 + x1*wh1 + bh;
                float zv = x0*wz0 + x1*wz1 + bz;
                size_t base = (size_t)r*64 + t;
                d_h[base] = hv; d_z[base] = zv;
                sh[j*64+t] = hv; sz[j*64+t] = zv;
            }
        } else {
            float scp = (times[step] - times[step-1]) * (1.f/6.f);
            #pragma unroll
            for (int j=0;j<8;j++){
                size_t base = (size_t)(r0+j)*64 + t;
                float hv = d_h[base] + scp*d_acch[base];
                float zv = d_z[base] + scp*d_accz[base];
                d_h[base] = hv; d_z[base] = zv;
                sh[j*64+t] = hv; sz[j*64+t] = zv;
            }
        }
    } else {
        #pragma unroll
        for (int j=0;j<8;j++){
            size_t base = (size_t)(r0+j)*64 + t;
            sh[j*64+t] = d_h[base] + c*d_kh[base];
            sz[j*64+t] = d_z[base] + c*d_kz[base];
        }
    }
    __syncthreads();

    float af[8], ag[8];
    float bf = fbin[t], bg = gbin[t];
    #pragma unroll
    for (int j=0;j<8;j++){ af[j]=bf; ag[j]=bg; }
    #pragma unroll 8
    for (int i=0;i<64;i++){
        float wf = fWin[i*64+t];
        float wg = gWin[i*64+t];
        #pragma unroll
        for (int j=0;j<8;j++){
            af[j] = fmaf(sh[j*64+i], wf, af[j]);
            ag[j] = fmaf(sz[j*64+i], wg, ag[j]);
        }
    }
    // write x1g transposed: x1gT[n][b*64+t]
    #pragma unroll
    for (int j=0;j<8;j++){
        int r = r0+j;
        int b = r/Nn, n = r - b*Nn;
        d_x1gT[(size_t)n*1024 + b*64 + t] = fmaxf(ag[j], 0.f);
    }
    #pragma unroll
    for (int j=0;j<8;j++) sx[j*64+t] = fmaxf(af[j], 0.f);
    __syncthreads();

    float bm = fbmid[t];
    #pragma unroll
    for (int j=0;j<8;j++) af[j]=bm;
    #pragma unroll 8
    for (int i=0;i<64;i++){
        float wf = fWmid[i*64+t];
        #pragma unroll
        for (int j=0;j<8;j++) af[j] = fmaf(sx[j*64+i], wf, af[j]);
    }
    __syncthreads();
    #pragma unroll
    for (int j=0;j<8;j++) sz[j*64+t] = fmaxf(af[j], 0.f);
    __syncthreads();

    float2 b3 = ((const float2*)fbout)[t];
    float2 a3[8];
    #pragma unroll
    for (int j=0;j<8;j++) a3[j]=b3;
    #pragma unroll 8
    for (int i=0;i<64;i++){
        float2 wv = ((const float2*)fWout)[i*64 + t];
        #pragma unroll
        for (int j=0;j<8;j++){
            a3[j].x = fmaf(sz[j*64+i], wv.x, a3[j].x);
            a3[j].y = fmaf(sz[j*64+i], wv.y, a3[j].y);
        }
    }

    int idx = 0;
    #pragma unroll
    for (int jj=1; jj<=NSTEP-1; jj++) if (times[jj] <= tv) idx = jj;
    float frac = tv - times[idx];
    #pragma unroll
    for (int j=0;j<8;j++){
        size_t cbase = ((size_t)(r0+j)*NSTEP + idx)*2;
        float dX0 = cb[cbase]   + (cc[cbase]   + cd[cbase]  *frac)*frac;
        float dX1 = cb[cbase+1] + (cc[cbase+1] + cd[cbase+1]*frac)*frac;
        float dh = fast_tanh(a3[j].x)*dX0 + fast_tanh(a3[j].y)*dX1;
        size_t base = (size_t)(r0+j)*64 + t;
        d_kh[base] = dh;
        d_acch[base] = (stage==0) ? dh : (d_acch[base] + w*dh);
    }
}

// graph aggregation as tiled GEMM: yT[307,1024] = A[307,320] @ x1gT[320,1024]
// 32x128 tile, grid (10,8), 256 threads, f32x2 FMA.
#define AGG_SMEM ((64*32*2 + 64*128)*4)   // As2 (dup) 16KB + Xs 32KB
__global__ void __launch_bounds__(256) k_agg(){
    extern __shared__ float sm[];
    float2* As2 = (float2*)sm;          // [k][row] duplicated, stride 32
    float*  Xs  = sm + 64*32*2;         // [k][128]
    int tid = threadIdx.x;
    int n0 = blockIdx.x * 32;
    int c0 = blockIdx.y * 128;
    int tx = tid & 31, ty = tid >> 5;

    ull acc[4][2];
    #pragma unroll
    for (int i=0;i<4;i++){ acc[i][0]=0ull; acc[i][1]=0ull; }

    for (int kb = 0; kb < AGK; kb += 64){
        __syncthreads();
        #pragma unroll
        for (int it=0; it<2; it++){
            int u = it*256 + tid;            // 512 float4 = 32 rows x 64 k
            int rr = u >> 4, k4 = u & 15;
            float4 v = *(const float4*)&d_A[(size_t)(n0+rr)*AGK + kb + k4*4];
            As2[(k4*4+0)*32 + rr] = make_float2(v.x,v.x);
            As2[(k4*4+1)*32 + rr] = make_float2(v.y,v.y);
            As2[(k4*4+2)*32 + rr] = make_float2(v.z,v.z);
            As2[(k4*4+3)*32 + rr] = make_float2(v.w,v.w);
        }
        #pragma unroll
        for (int it=0; it<8; it++){
            int u = it*256 + tid;            // 2048 float4 = 64 k x 128 c
            int kk = u >> 5, c4 = u & 31;
            *(float4*)&Xs[kk*128 + c4*4] =
                *(const float4*)&d_x1gT[(size_t)(kb+kk)*1024 + c0 + c4*4];
        }
        __syncthreads();

        #pragma unroll 4
        for (int k=0;k<64;k++){
            float4 bv = *(const float4*)&Xs[k*128 + tx*4];
            ull b0,b1;
            asm("mov.b64 %0,{%1,%2};" : "=l"(b0) : "f"(bv.x), "f"(bv.y));
            asm("mov.b64 %0,{%1,%2};" : "=l"(b1) : "f"(bv.z), "f"(bv.w));
            const ull* Ar = (const ull*)&As2[k*32 + ty*4];
            #pragma unroll
            for (int i=0;i<4;i++){
                ull a2 = Ar[i];
                asm("fma.rn.f32x2 %0, %1, %2, %0;" : "+l"(acc[i][0]) : "l"(a2), "l"(b0));
                asm("fma.rn.f32x2 %0, %1, %2, %0;" : "+l"(acc[i][1]) : "l"(a2), "l"(b1));
            }
        }
    }
    #pragma unroll
    for (int i=0;i<4;i++){
        int n = n0 + ty*4 + i;
        if (n < Nn){
            float4 v;
            asm("mov.b64 {%0,%1},%2;" : "=f"(v.x), "=f"(v.y) : "l"(acc[i][0]));
            asm("mov.b64 {%0,%1},%2;" : "=f"(v.z), "=f"(v.w) : "l"(acc[i][1]));
            *(float4*)&d_yT[(size_t)n*1024 + c0 + tx*4] = v;
        }
    }
}

// AGC per node; x1gT/yT rows are contiguous now
__global__ void __launch_bounds__(256) k_x2(){
    __shared__ float sx[16*64], sy[16*64];
    int n = blockIdx.x, tid = threadIdx.x;
    #pragma unroll
    for (int it=0; it<4; it++){
        int u = it*256 + tid;
        sx[u] = d_x1gT[(size_t)n*1024 + u];
        sy[u] = d_yT[(size_t)n*1024 + u];
    }
    __syncthreads();
    int o = tid & 63, bg = tid >> 6;
    const float* W0 = &d_agcW[(size_t)n*8192];
    const float* W1 = W0 + 4096;
    float bias = d_agcb[n*64+o];
    float acc[4] = {bias, bias, bias, bias};
    #pragma unroll 4
    for (int i=0;i<64;i++){
        float w0 = W0[i*64+o];
        float w1 = W1[i*64+o];
        #pragma unroll
        for (int j=0;j<4;j++){
            int b = bg*4 + j;
            acc[j] = fmaf(sx[b*64+i], w0, acc[j]);
            acc[j] = fmaf(sy[b*64+i], w1, acc[j]);
        }
    }
    #pragma unroll
    for (int j=0;j<4;j++){
        int b = bg*4 + j;
        d_x2[((size_t)b*Nn + n)*64 + o] = fmaxf(acc[j], 0.f);
    }
}

// big fused GEMM+tanh+contract (unchanged from R3)
#define GZ_X2STRIDE 130
#define GZ_SMEM ((64*GZ_X2STRIDE*2 + 64*256 + 256)*4)

__global__ void __launch_bounds__(512) k_gz(
                     const float* __restrict__ gWout, const float* __restrict__ gbout,
                     int stage){
    extern __shared__ float sm[];
    float2* Xs2 = (float2*)sm;
    float* Ws = sm + 64*GZ_X2STRIDE*2;
    float* sb = Ws + 64*256;
    int tid = threadIdx.x;
    int r0 = blockIdx.x * 128;
    int c0 = blockIdx.y * 256;

    #pragma unroll
    for (int it=0; it<4; it++){
        int u = it*512 + tid;
        int row = u >> 4, kq = u & 15;
        int r = r0 + row;
        float4 v = (r < Rr) ? *(const float4*)&d_x2[(size_t)r*64 + kq*4]
                            : make_float4(0.f,0.f,0.f,0.f);
        Xs2[(kq*4+0)*GZ_X2STRIDE + row] = make_float2(v.x, v.x);
        Xs2[(kq*4+1)*GZ_X2STRIDE + row] = make_float2(v.y, v.y);
        Xs2[(kq*4+2)*GZ_X2STRIDE + row] = make_float2(v.z, v.z);
        Xs2[(kq*4+3)*GZ_X2STRIDE + row] = make_float2(v.w, v.w);
    }
    #pragma unroll
    for (int it=0; it<8; it++){
        int u = it*512 + tid;
        int k = u >> 6, c4 = u & 63;
        *(float4*)&Ws[k*256 + c4*4] = *(const float4*)&gWout[(size_t)k*4096 + c0 + c4*4];
    }
    if (tid < 256) sb[tid] = gbout[c0 + tid];
    __syncthreads();

    int tx = tid & 31, ty = tid >> 5;
    ull acc[8][4];
    #pragma unroll
    for (int i=0;i<8;i++)
        #pragma unroll
        for (int p=0;p<4;p++) acc[i][p] = 0ull;

    #pragma unroll 2
    for (int k=0;k<64;k++){
        float4 bA  = *(const float4*)&Ws[k*256 + tx*4];
        float4 bB  = *(const float4*)&Ws[k*256 + 128 + tx*4];
        ull b0,b1,b2,b3;
        asm("mov.b64 %0,{%1,%2};" : "=l"(b0) : "f"(bA.x), "f"(bA.y));
        asm("mov.b64 %0,{%1,%2};" : "=l"(b1) : "f"(bA.z), "f"(bA.w));
        asm("mov.b64 %0,{%1,%2};" : "=l"(b2) : "f"(bB.x), "f"(bB.y));
        asm("mov.b64 %0,{%1,%2};" : "=l"(b3) : "f"(bB.z), "f"(bB.w));
        const ull* Xrow = (const ull*)&Xs2[k*GZ_X2STRIDE + ty*8];
        #pragma unroll
        for (int i=0;i<8;i++){
            ull a2 = Xrow[i];
            asm("fma.rn.f32x2 %0, %1, %2, %0;" : "+l"(acc[i][0]) : "l"(a2), "l"(b0));
            asm("fma.rn.f32x2 %0, %1, %2, %0;" : "+l"(acc[i][1]) : "l"(a2), "l"(b1));
            asm("fma.rn.f32x2 %0, %1, %2, %0;" : "+l"(acc[i][2]) : "l"(a2), "l"(b2));
            asm("fma.rn.f32x2 %0, %1, %2, %0;" : "+l"(acc[i][3]) : "l"(a2), "l"(b3));
        }
    }

    float w = (stage==1 || stage==2) ? 2.f : 1.f;
    int jb = (4*tx) & 63;
    float bA0 = sb[4*tx],       bA1 = sb[4*tx+1];
    float bA2 = sb[4*tx+2],     bA3 = sb[4*tx+3];
    float bB0 = sb[128+4*tx],   bB1 = sb[128+4*tx+1];
    float bB2 = sb[128+4*tx+2], bB3 = sb[128+4*tx+3];
    float sA[8], sB[8];
    #pragma unroll
    for (int i=0;i<8;i++){
        int r = r0 + ty*8 + i;
        float4 dhv = make_float4(0.f,0.f,0.f,0.f);
        if (r < Rr) dhv = *(const float4*)&d_kh[(size_t)r*64 + jb];
        float g0,g1;
        asm("mov.b64 {%0,%1},%2;" : "=f"(g0), "=f"(g1) : "l"(acc[i][0]));
        float s = fast_tanh(g0+bA0)*dhv.x + fast_tanh(g1+bA1)*dhv.y;
        asm("mov.b64 {%0,%1},%2;" : "=f"(g0), "=f"(g1) : "l"(acc[i][1]));
        s += fast_tanh(g0+bA2)*dhv.z + fast_tanh(g1+bA3)*dhv.w;
        sA[i] = s;
        asm("mov.b64 {%0,%1},%2;" : "=f"(g0), "=f"(g1) : "l"(acc[i][2]));
        s = fast_tanh(g0+bB0)*dhv.x + fast_tanh(g1+bB1)*dhv.y;
        asm("mov.b64 {%0,%1},%2;" : "=f"(g0), "=f"(g1) : "l"(acc[i][3]));
        s += fast_tanh(g0+bB2)*dhv.z + fast_tanh(g1+bB3)*dhv.w;
        sB[i] = s;
    }
    #pragma unroll
    for (int s2=1; s2<16; s2<<=1){
        #pragma unroll
        for (int i=0;i<8;i++){
            sA[i] += __shfl_xor_sync(0xffffffffu, sA[i], s2);
            sB[i] += __shfl_xor_sync(0xffffffffu, sB[i], s2);
        }
    }
    if (tx == 0 || tx == 16){
        int ihalf = (tx == 16) ? 1 : 0;
        int iA = blockIdx.y*4 + ihalf;
        int iB = iA + 2;
        #pragma unroll
        for (int i=0;i<8;i++){
            int r = r0 + ty*8 + i;
            if (r < Rr){
                size_t oA = (size_t)r*64 + iA;
                size_t oB = (size_t)r*64 + iB;
                d_kz[oA] = sA[i];
                d_kz[oB] = sB[i];
                d_accz[oA] = (stage==0) ? sA[i] : (d_accz[oA] + w*sA[i]);
                d_accz[oB] = (stage==0) ? sB[i] : (d_accz[oB] + w*sB[i]);
            }
        }
    }
}

// output conv; applies the final RK4 update to z
__global__ void k_out(const float* __restrict__ convW, const float* __restrict__ convb,
                      const float* __restrict__ times, float* __restrict__ out){
    __shared__ float szr[64];
    int r = blockIdx.x, t = threadIdx.x;
    float sc = (times[NSTEP] - times[NSTEP-1]) * (1.f/6.f);
    size_t base = (size_t)r*64 + t;
    szr[t] = d_z[base] + sc*d_accz[base];
    __syncthreads();
    if (t < 12){
        float acc = convb[t];
        #pragma unroll 8
        for (int h=0; h<64; h++) acc = fmaf(szr[h], convW[t*64+h], acc);
        int b = r / Nn, n = r - b*Nn;
        out[(size_t)(b*12 + t)*Nn + n] = acc;
    }
}

// ---------------- launcher ----------------
extern "C" void kernel_launch(void* const* d_in, const int* in_sizes, int n_in,
                              void* d_out, int out_size){
    const float* coeff_a = (const float*)d_in[0];
    const float* coeff_b = (const float*)d_in[1];
    const float* coeff_c = (const float*)d_in[2];
    const float* coeff_d = (const float*)d_in[3];
    const float* times   = (const float*)d_in[4];
    const float* h_W     = (const float*)d_in[5];
    const float* h_b     = (const float*)d_in[6];
    const float* z_W     = (const float*)d_in[7];
    const float* z_b     = (const float*)d_in[8];
    const float* f_W_in  = (const float*)d_in[9];
    const float* f_b_in  = (const float*)d_in[10];
    const float* f_W_mid = (const float*)d_in[11];
    const float* f_b_mid = (const float*)d_in[12];
    const float* f_W_out = (const float*)d_in[13];
    const float* f_b_out = (const float*)d_in[14];
    const float* g_W_in  = (const float*)d_in[15];
    const float* g_b_in  = (const float*)d_in[16];
    const float* g_E     = (const float*)d_in[17];
    const float* g_Wpool = (const float*)d_in[18];
    const float* g_bpool = (const float*)d_in[19];
    const float* g_W_out = (const float*)d_in[20];
    const float* g_b_out = (const float*)d_in[21];
    const float* conv_W  = (const float*)d_in[22];
    const float* conv_b  = (const float*)d_in[23];
    float* out = (float*)d_out;

    cudaFuncSetAttribute(k_agg, cudaFuncAttributeMaxDynamicSharedMemorySize, AGG_SMEM);
    cudaFuncSetAttribute(k_gz,  cudaFuncAttributeMaxDynamicSharedMemorySize, GZ_SMEM);

    k_pre<<<Nn + PRE_AGCB_BLKS + PRE_AGCW_BLKS, 256>>>(g_E, g_bpool, g_Wpool);

    for (int step = 0; step < NSTEP; step++){
        for (int stage = 0; stage < 4; stage++){
            k_fg1<<<Rr/8, 64>>>(times, coeff_a, coeff_b, coeff_c, coeff_d,
                                h_W, h_b, z_W, z_b,
                                f_W_in, f_b_in, f_W_mid, f_b_mid, f_W_out, f_b_out,
                                g_W_in, g_b_in, step, stage);
            k_agg<<<dim3(10,8), 256, AGG_SMEM>>>();
            k_x2<<<Nn, 256>>>();
            k_gz<<<dim3(39,16), 512, GZ_SMEM>>>(g_W_out, g_b_out, stage);
        }
    }
    k_out<<<Rr, 64>>>(conv_W, conv_b, times, out);
}